// round 3
// baseline (speedup 1.0000x reference)
#include <cuda_runtime.h>
#include <cstdint>

#define HW 327680          // 512*640
#define KTOT 20480
#define KC 320             // K-chunk per block
#define KS 32              // smem stage depth

typedef unsigned long long ull;

__device__ float g_aud[384 * 128];
__device__ float g_vis[128 * 128];

__device__ __forceinline__ ull dupf(float x) {
    ull r;
    asm("mov.b64 %0, {%1, %1};" : "=l"(r) : "r"(__float_as_uint(x)));
    return r;
}
__device__ __forceinline__ void ffma2(ull& d, ull a, ull b) {
    asm("fma.rn.f32x2 %0, %1, %2, %3;" : "=l"(d) : "l"(a), "l"(b), "l"(d));
}
__device__ __forceinline__ float lo2(ull v) { return __uint_as_float((unsigned)v); }
__device__ __forceinline__ float hi2(ull v) { return __uint_as_float((unsigned)(v >> 32)); }

__global__ void zero_kernel() {
    int i = blockIdx.x * 256 + threadIdx.x;
    if (i < 384 * 128) g_aud[i] = 0.0f;
    if (i < 128 * 128) g_vis[i] = 0.0f;
}

// Split-K GEMM with fused stride-4 gather.
// grid.x = 8 M-tiles (0..5 -> aud rows 0..383, 6..7 -> vis rows 0..127)
// grid.y = 64 K-chunks of 320
__global__ __launch_bounds__(256) void gemm_kernel(
    const float* __restrict__ f1, const float* __restrict__ f2,
    const float* __restrict__ W1, const float* __restrict__ W2)
{
    __shared__ __align__(16) float As[2][64][KS];    // [buf][row][kk] 16KB
    __shared__ __align__(16) float Ws[2][KS][128];   // [buf][kk][col] 32KB

    const int tid = threadIdx.x;
    const int wid = tid >> 5, lane = tid & 31;
    const int mt = blockIdx.x;
    const bool isVis = (mt >= 6);
    const float* __restrict__ src = isVis ? f2 : f1;
    const float* __restrict__ Wm  = isVis ? W2 : W1;
    float* gout = isVis ? g_vis : g_aud;
    const int row0 = (isVis ? (mt - 6) : mt) * 64;
    const int kc0 = blockIdx.y * KC;

    const float* __restrict__ abase = src + (size_t)(row0 + wid * 8) * HW;
    const float* __restrict__ wbase = Wm + (size_t)(tid & 127) * KTOT + kc0;
    const int whalf = tid >> 7;   // 0 or 1
    const int wc = tid & 127;

    float aR[8];
    float4 wR[4];

    auto loadStage = [&](int s) {
        int d = kc0 + s * KS + lane;
        unsigned hh = (unsigned)d / 160u;
        unsigned ww = (unsigned)d - hh * 160u;
        size_t off = (size_t)hh * 2560u + (size_t)ww * 4u;
#pragma unroll
        for (int it = 0; it < 8; ++it)
            aR[it] = __ldg(abase + (size_t)it * HW + off);
        const float* wp = wbase + s * KS;
#pragma unroll
        for (int t = 0; t < 4; ++t)
            wR[t] = *reinterpret_cast<const float4*>(wp + (whalf + 2 * t) * 4);
    };
    auto storeStage = [&](int buf) {
#pragma unroll
        for (int it = 0; it < 8; ++it)
            As[buf][wid * 8 + it][lane] = aR[it];
#pragma unroll
        for (int t = 0; t < 4; ++t) {
            int kk = (whalf + 2 * t) * 4;
            Ws[buf][kk + 0][wc] = wR[t].x;
            Ws[buf][kk + 1][wc] = wR[t].y;
            Ws[buf][kk + 2][wc] = wR[t].z;
            Ws[buf][kk + 3][wc] = wR[t].w;
        }
    };

    ull acc[8][2];
#pragma unroll
    for (int r = 0; r < 8; ++r) { acc[r][0] = 0ull; acc[r][1] = 0ull; }

    loadStage(0);
    storeStage(0);
    __syncthreads();

    const int tx = lane, ty = wid;
    const int NSTAGE = KC / KS;   // 10
    for (int s = 0; s < NSTAGE; ++s) {
        int buf = s & 1;
        if (s + 1 < NSTAGE) loadStage(s + 1);
#pragma unroll
        for (int kk = 0; kk < KS; ++kk) {
            ulonglong2 wv = *reinterpret_cast<const ulonglong2*>(&Ws[buf][kk][tx * 4]);
#pragma unroll
            for (int r = 0; r < 8; ++r) {
                ull ad = dupf(As[buf][ty * 8 + r][kk]);
                ffma2(acc[r][0], ad, wv.x);
                ffma2(acc[r][1], ad, wv.y);
            }
        }
        if (s + 1 < NSTAGE) storeStage(buf ^ 1);
        __syncthreads();
    }

#pragma unroll
    for (int r = 0; r < 8; ++r) {
        int row = row0 + ty * 8 + r;
        float* op = gout + row * 128 + tx * 4;
        atomicAdd(op + 0, lo2(acc[r][0]));
        atomicAdd(op + 1, hi2(acc[r][0]));
        atomicAdd(op + 2, lo2(acc[r][1]));
        atomicAdd(op + 3, hi2(acc[r][1]));
    }
}

// Per-(batch, modality, k-half) attention epilogue. grid = 512, block = 256.
__global__ __launch_bounds__(256) void attn_kernel(
    const float* __restrict__ b1, const float* __restrict__ b2,
    const float* __restrict__ Aa, const float* __restrict__ Av,
    const float* __restrict__ Wa, const float* __restrict__ Wv,
    const float* __restrict__ Wca, const float* __restrict__ Wcv,
    const float* __restrict__ Wha, const float* __restrict__ Whv,
    float* __restrict__ out)
{
    __shared__ float enc_a[384];                 // aud[c][k] + b1
    __shared__ float visr[128];                  // vis row + b2
    __shared__ float XAv[768];                   // (Aa or Av) @ av : [i][m]
    __shared__ __align__(8) float att[8 * 256];  // per-warp tanh row
    __shared__ __align__(8) float Wct[8448];     // Wc paired-transposed: [(m/2)*33+h]*2 + (m&1)
    __shared__ float Wx_s[96];                   // Wa/Wv (32x3)
    __shared__ float Wh_s[96];                   // Wha/Whv (3x32)

    const int tid = threadIdx.x;
    const int z = blockIdx.x;
    const int b = z >> 2;
    const int mod = (z >> 1) & 1;   // 0 = audio, 1 = visual
    const int khalf = z & 1;

    if (tid < 128) visr[tid] = g_vis[b * 128 + tid] + b2[tid];
    for (int i = tid; i < 384; i += 256)
        enc_a[i] = g_aud[b * 384 + i] + b1[i & 127];
    __syncthreads();

    const float* M = mod ? Av : Aa;
    {
        int m = tid;  // 0..255
        float av0 = (m < 128) ? enc_a[m]       : visr[m - 128];
        float av1 = (m < 128) ? enc_a[128 + m] : visr[m - 128];
        float av2 = (m < 128) ? enc_a[256 + m] : visr[m - 128];
        XAv[m]       = M[0] * av0 + M[1] * av1 + M[2] * av2;
        XAv[256 + m] = M[3] * av0 + M[4] * av1 + M[5] * av2;
        XAv[512 + m] = M[6] * av0 + M[7] * av1 + M[8] * av2;
    }
    const float* Wc = mod ? Wcv : Wca;
    for (int idx = tid; idx < 8192; idx += 256) {
        int h = idx >> 8, m = idx & 255;
        Wct[((m >> 1) * 33 + h) * 2 + (m & 1)] = Wc[idx];
    }
    if (tid < 96) {
        Wx_s[tid] = (mod ? Wv : Wa)[tid];
        Wh_s[tid] = (mod ? Whv : Wha)[tid];
    }
    __syncthreads();

    const int wid = tid >> 5, lane = tid & 31;
    const float scale = 0.0625f;   // 1/sqrt(256)
    float* attw = &att[wid * 256];

    for (int t = 0; t < 8; ++t) {
        int k = khalf * 64 + wid * 8 + t;
        float e0, e1, e2;
        if (mod == 0) { e0 = enc_a[k]; e1 = enc_a[128 + k]; e2 = enc_a[256 + k]; }
        else          { e0 = visr[k];  e1 = e0;             e2 = e0; }

#pragma unroll
        for (int j = 0; j < 8; ++j) {
            int m = lane + 32 * j;
            float s = e0 * XAv[m] + e1 * XAv[256 + m] + e2 * XAv[512 + m];
            attw[m] = tanhf(s * scale);
        }
        __syncwarp();

        // H[k][h] for h = lane
        int h = lane;
        float accs = e0 * Wx_s[h * 3] + e1 * Wx_s[h * 3 + 1] + e2 * Wx_s[h * 3 + 2];
        ull acc2 = 0ull;
        const ull* ap = reinterpret_cast<const ull*>(attw);
#pragma unroll 4
        for (int m2 = 0; m2 < 128; ++m2) {
            ull av_ = ap[m2];                                        // broadcast
            ull wv_ = *reinterpret_cast<const ull*>(&Wct[(m2 * 33 + h) * 2]);
            ffma2(acc2, av_, wv_);
        }
        float Hh = fmaxf(accs + lo2(acc2) + hi2(acc2), 0.0f);

        float r0 = Hh * Wh_s[h];
        float r1 = Hh * Wh_s[32 + h];
        float r2 = Hh * Wh_s[64 + h];
#pragma unroll
        for (int o = 16; o; o >>= 1) {
            r0 += __shfl_xor_sync(0xffffffffu, r0, o);
            r1 += __shfl_xor_sync(0xffffffffu, r1, o);
            r2 += __shfl_xor_sync(0xffffffffu, r2, o);
        }
        if (lane == 0) {
            float* ob = out + (size_t)b * 768 + mod * 128 + k;
            float ea0, ea1, ea2;
            if (mod == 0) { ea0 = enc_a[k]; ea1 = enc_a[128 + k]; ea2 = enc_a[256 + k]; }
            else          { ea0 = visr[k];  ea1 = ea0;            ea2 = ea0; }
            ob[0]   = r0 + ea0;
            ob[256] = r1 + ea1;
            ob[512] = r2 + ea2;
        }
        __syncwarp();
    }
}

extern "C" void kernel_launch(void* const* d_in, const int* in_sizes, int n_in,
                              void* d_out, int out_size)
{
    const float* f1  = (const float*)d_in[0];
    const float* f2  = (const float*)d_in[1];
    const float* W1  = (const float*)d_in[2];
    const float* b1  = (const float*)d_in[3];
    const float* W2  = (const float*)d_in[4];
    const float* b2  = (const float*)d_in[5];
    const float* Aa  = (const float*)d_in[6];
    const float* Av  = (const float*)d_in[7];
    const float* Wa  = (const float*)d_in[8];
    const float* Wv  = (const float*)d_in[9];
    const float* Wca = (const float*)d_in[10];
    const float* Wcv = (const float*)d_in[11];
    const float* Wha = (const float*)d_in[12];
    const float* Whv = (const float*)d_in[13];
    float* out = (float*)d_out;

    zero_kernel<<<192, 256>>>();
    dim3 g(8, 64);
    gemm_kernel<<<g, 256>>>(f1, f2, W1, W2);
    attn_kernel<<<512, 256>>>(b1, b2, Aa, Av, Wa, Wv, Wca, Wcv, Wha, Whv, out);
}

// round 4
// speedup vs baseline: 1.2312x; 1.2312x over previous
#include <cuda_runtime.h>
#include <cstdint>

#define HW 327680          // 512*640
#define KTOT 20480
#define KC 640             // K-chunk per block
#define KS 32              // smem stage depth

typedef unsigned long long ull;

__device__ float g_aud[384 * 128];
__device__ float g_vis[128 * 128];

__device__ __forceinline__ ull dupf(float x) {
    ull r;
    asm("mov.b64 %0, {%1, %1};" : "=l"(r) : "r"(__float_as_uint(x)));
    return r;
}
__device__ __forceinline__ void ffma2(ull& d, ull a, ull b) {
    asm("fma.rn.f32x2 %0, %1, %2, %3;" : "=l"(d) : "l"(a), "l"(b), "l"(d));
}
__device__ __forceinline__ float lo2(ull v) { return __uint_as_float((unsigned)v); }
__device__ __forceinline__ float hi2(ull v) { return __uint_as_float((unsigned)(v >> 32)); }

__device__ __forceinline__ float ftanh(float x) {
    float xc = fminf(fmaxf(x, -20.0f), 20.0f);
    float e = __expf(2.0f * xc);
    return 1.0f - __fdividef(2.0f, e + 1.0f);
}

__global__ void zero_kernel() {
    int i = blockIdx.x * 256 + threadIdx.x;
    if (i < 384 * 128) g_aud[i] = 0.0f;
    if (i < 128 * 128) g_vis[i] = 0.0f;
}

// Split-K GEMM with fused stride-4 gather.
// grid.x = 8 M-tiles (0..5 -> aud rows 0..383, 6..7 -> vis rows 0..127)
// grid.y = 32 K-chunks of 640
__global__ __launch_bounds__(256) void gemm_kernel(
    const float* __restrict__ f1, const float* __restrict__ f2,
    const float* __restrict__ W1, const float* __restrict__ W2)
{
    __shared__ __align__(16) float As[2][64][KS];    // 16KB
    __shared__ __align__(16) float Ws[2][KS][128];   // 32KB

    const int tid = threadIdx.x;
    const int wid = tid >> 5, lane = tid & 31;
    const int mt = blockIdx.x;
    const bool isVis = (mt >= 6);
    const float* __restrict__ src = isVis ? f2 : f1;
    const float* __restrict__ Wm  = isVis ? W2 : W1;
    float* gout = isVis ? g_vis : g_aud;
    const int row0 = (isVis ? (mt - 6) : mt) * 64;
    const int kc0 = blockIdx.y * KC;

    const float* __restrict__ abase = src + (size_t)(row0 + wid * 8) * HW;
    const float* __restrict__ wbase = Wm + (size_t)(tid & 127) * KTOT + kc0;
    const int whalf = tid >> 7;   // 0 or 1
    const int wc = tid & 127;

    float aR[8];
    float4 wR[4];

    auto loadStage = [&](int s) {
        int d = kc0 + s * KS + lane;
        unsigned hh = (unsigned)d / 160u;
        unsigned ww = (unsigned)d - hh * 160u;
        size_t off = (size_t)hh * 2560u + (size_t)ww * 4u;
#pragma unroll
        for (int it = 0; it < 8; ++it)
            aR[it] = __ldg(abase + (size_t)it * HW + off);
        const float* wp = wbase + s * KS;
#pragma unroll
        for (int t = 0; t < 4; ++t)
            wR[t] = *reinterpret_cast<const float4*>(wp + (whalf + 2 * t) * 4);
    };
    auto storeStage = [&](int buf) {
#pragma unroll
        for (int it = 0; it < 8; ++it)
            As[buf][wid * 8 + it][lane] = aR[it];
#pragma unroll
        for (int t = 0; t < 4; ++t) {
            int kk = (whalf + 2 * t) * 4;
            Ws[buf][kk + 0][wc] = wR[t].x;
            Ws[buf][kk + 1][wc] = wR[t].y;
            Ws[buf][kk + 2][wc] = wR[t].z;
            Ws[buf][kk + 3][wc] = wR[t].w;
        }
    };

    ull acc[8][2];
#pragma unroll
    for (int r = 0; r < 8; ++r) { acc[r][0] = 0ull; acc[r][1] = 0ull; }

    loadStage(0);
    storeStage(0);
    __syncthreads();

    const int tx = lane, ty = wid;
    const int NSTAGE = KC / KS;   // 20
    for (int s = 0; s < NSTAGE; ++s) {
        int buf = s & 1;
        if (s + 1 < NSTAGE) loadStage(s + 1);
#pragma unroll
        for (int kk = 0; kk < KS; ++kk) {
            ulonglong2 wv = *reinterpret_cast<const ulonglong2*>(&Ws[buf][kk][tx * 4]);
#pragma unroll
            for (int r = 0; r < 8; ++r) {
                ull ad = dupf(As[buf][ty * 8 + r][kk]);
                ffma2(acc[r][0], ad, wv.x);
                ffma2(acc[r][1], ad, wv.y);
            }
        }
        if (s + 1 < NSTAGE) storeStage(buf ^ 1);
        __syncthreads();
    }

#pragma unroll
    for (int r = 0; r < 8; ++r) {
        int row = row0 + ty * 8 + r;
        float* op = gout + row * 128 + tx * 4;
        atomicAdd(op + 0, lo2(acc[r][0]));
        atomicAdd(op + 1, hi2(acc[r][0]));
        atomicAdd(op + 2, lo2(acc[r][1]));
        atomicAdd(op + 3, hi2(acc[r][1]));
    }
}

// Per-(batch, modality) attention epilogue. grid = 256, block = 256.
// Dynamic smem layout (floats):
//   enc_a [0,384)  visr [384,512)  XAv [512,1280)
//   Wx [1280,1376)  Wh [1376,1472)  (pad)
//   Wcs [1536, 1536+32*260)        att [9856, 9856+16384)
#define SM_ENC   0
#define SM_VIS   384
#define SM_XAV   512
#define SM_WX    1280
#define SM_WH    1376
#define SM_WCS   1536
#define SM_ATT   9856
#define SM_TOTAL 26240   // floats -> 104960 bytes

__global__ __launch_bounds__(256) void attn_kernel(
    const float* __restrict__ b1, const float* __restrict__ b2,
    const float* __restrict__ Aa, const float* __restrict__ Av,
    const float* __restrict__ Wa, const float* __restrict__ Wv,
    const float* __restrict__ Wca, const float* __restrict__ Wcv,
    const float* __restrict__ Wha, const float* __restrict__ Whv,
    float* __restrict__ out)
{
    extern __shared__ __align__(16) float smem[];
    float* enc_a = smem + SM_ENC;
    float* visr  = smem + SM_VIS;
    float* XAv   = smem + SM_XAV;
    float* Wx_s  = smem + SM_WX;
    float* Wh_s  = smem + SM_WH;
    float* Wcs   = smem + SM_WCS;
    float* att   = smem + SM_ATT;

    const int tid = threadIdx.x;
    const int b = blockIdx.x >> 1;
    const int mod = blockIdx.x & 1;   // 0 = audio, 1 = visual

    if (tid < 128) visr[tid] = g_vis[b * 128 + tid] + b2[tid];
    for (int i = tid; i < 384; i += 256)
        enc_a[i] = g_aud[b * 384 + i] + b1[i & 127];
    if (tid < 96) {
        Wx_s[tid] = (mod ? Wv : Wa)[tid];
        Wh_s[tid] = (mod ? Whv : Wha)[tid];
    }
    const float* Wc = mod ? Wcv : Wca;
    for (int idx = tid; idx < 8192; idx += 256) {
        int h = idx >> 8, m = idx & 255;
        Wcs[h * 260 + m] = Wc[idx];
    }
    __syncthreads();

    const float* M = mod ? Av : Aa;
    {
        int m = tid;  // 0..255
        float av0 = (m < 128) ? enc_a[m]       : visr[m - 128];
        float av1 = (m < 128) ? enc_a[128 + m] : visr[m - 128];
        float av2 = (m < 128) ? enc_a[256 + m] : visr[m - 128];
        XAv[m]       = M[0] * av0 + M[1] * av1 + M[2] * av2;
        XAv[256 + m] = M[3] * av0 + M[4] * av1 + M[5] * av2;
        XAv[512 + m] = M[6] * av0 + M[7] * av1 + M[8] * av2;
    }
    __syncthreads();

    const int wid = tid >> 5, h = tid & 31;
    float* arow = att + wid * 2048;        // 8 rows x 256 per warp
    const float wx0 = Wx_s[h * 3], wx1 = Wx_s[h * 3 + 1], wx2 = Wx_s[h * 3 + 2];
    const float wh0 = Wh_s[h], wh1 = Wh_s[32 + h], wh2 = Wh_s[64 + h];
    const float scale = 0.0625f;   // 1/sqrt(256)

    for (int g = 0; g < 2; ++g) {
        const int k0 = wid * 16 + g * 8;

        float e0[8], e1[8], e2[8];
#pragma unroll
        for (int r = 0; r < 8; ++r) {
            int k = k0 + r;
            if (mod == 0) { e0[r] = enc_a[k]; e1[r] = enc_a[128 + k]; e2[r] = enc_a[256 + k]; }
            else          { e0[r] = visr[k];  e1[r] = e0[r];          e2[r] = e0[r]; }
        }

        // Phase 1: tanh rows into per-warp smem strip (lane = m%32)
#pragma unroll
        for (int mc = 0; mc < 8; ++mc) {
            int m = mc * 32 + h;
            float x0 = XAv[m], x1 = XAv[256 + m], x2 = XAv[512 + m];
#pragma unroll
            for (int r = 0; r < 8; ++r) {
                float s = e0[r] * x0 + e1[r] * x1 + e2[r] * x2;
                arow[r * 256 + m] = ftanh(s * scale);
            }
        }
        __syncwarp();

        // Phase 2: H[k][h] = relu(att_row . Wc[h] + e.Wx[h]) with f32x2 blocking
        ull acc[8];
#pragma unroll
        for (int r = 0; r < 8; ++r) acc[r] = 0ull;

        const ulonglong2* wrow = reinterpret_cast<const ulonglong2*>(Wcs + h * 260);
#pragma unroll 2
        for (int m4 = 0; m4 < 64; ++m4) {
            ulonglong2 wv = wrow[m4];
#pragma unroll
            for (int r = 0; r < 8; ++r) {
                ulonglong2 av = *reinterpret_cast<const ulonglong2*>(arow + r * 256 + m4 * 4);
                ffma2(acc[r], av.x, wv.x);
                ffma2(acc[r], av.y, wv.y);
            }
        }

#pragma unroll
        for (int r = 0; r < 8; ++r) {
            float pre = e0[r] * wx0 + e1[r] * wx1 + e2[r] * wx2;
            float Hh = fmaxf(lo2(acc[r]) + hi2(acc[r]) + pre, 0.0f);
            float r0 = Hh * wh0;
            float r1 = Hh * wh1;
            float r2 = Hh * wh2;
#pragma unroll
            for (int o = 16; o; o >>= 1) {
                r0 += __shfl_xor_sync(0xffffffffu, r0, o);
                r1 += __shfl_xor_sync(0xffffffffu, r1, o);
                r2 += __shfl_xor_sync(0xffffffffu, r2, o);
            }
            if (h == 0) {
                int k = k0 + r;
                float* ob = out + (size_t)b * 768 + mod * 128 + k;
                ob[0]   = r0 + e0[r];
                ob[256] = r1 + e1[r];
                ob[512] = r2 + e2[r];
            }
        }
        __syncwarp();
    }
}

extern "C" void kernel_launch(void* const* d_in, const int* in_sizes, int n_in,
                              void* d_out, int out_size)
{
    const float* f1  = (const float*)d_in[0];
    const float* f2  = (const float*)d_in[1];
    const float* W1  = (const float*)d_in[2];
    const float* b1  = (const float*)d_in[3];
    const float* W2  = (const float*)d_in[4];
    const float* b2  = (const float*)d_in[5];
    const float* Aa  = (const float*)d_in[6];
    const float* Av  = (const float*)d_in[7];
    const float* Wa  = (const float*)d_in[8];
    const float* Wv  = (const float*)d_in[9];
    const float* Wca = (const float*)d_in[10];
    const float* Wcv = (const float*)d_in[11];
    const float* Wha = (const float*)d_in[12];
    const float* Whv = (const float*)d_in[13];
    float* out = (float*)d_out;

    cudaFuncSetAttribute(attn_kernel, cudaFuncAttributeMaxDynamicSharedMemorySize,
                         SM_TOTAL * sizeof(float));

    zero_kernel<<<192, 256>>>();
    dim3 g(8, 32);
    gemm_kernel<<<g, 256>>>(f1, f2, W1, W2);
    attn_kernel<<<256, 256, SM_TOTAL * sizeof(float)>>>(
        b1, b2, Aa, Av, Wa, Wv, Wca, Wcv, Wha, Whv, out);
}

// round 5
// speedup vs baseline: 1.2811x; 1.0405x over previous
#include <cuda_runtime.h>
#include <cstdint>

#define HW 327680          // 512*640 per (b,c) image
#define KTOT 20480
#define KC 640             // K-chunk per split-K block (640 = 4 * 160)
#define KS 32              // smem stage depth
#define SPLITK 32
#define NSTG (KC / KS)     // 20

typedef unsigned long long ull;

__device__ float g_part[SPLITK][512][128];   // split-K partials, 8.4 MB

__device__ __forceinline__ ull dupf(float x) {
    ull r;
    asm("mov.b64 %0, {%1, %1};" : "=l"(r) : "r"(__float_as_uint(x)));
    return r;
}
__device__ __forceinline__ void ffma2(ull& d, ull a, ull b) {
    asm("fma.rn.f32x2 %0, %1, %2, %3;" : "=l"(d) : "l"(a), "l"(b), "l"(d));
}
__device__ __forceinline__ float lo2(ull v) { return __uint_as_float((unsigned)v); }
__device__ __forceinline__ float hi2(ull v) { return __uint_as_float((unsigned)(v >> 32)); }

__device__ __forceinline__ float ftanh(float x) {
    float xc = fminf(fmaxf(x, -20.0f), 20.0f);
    float e = __expf(2.0f * xc);
    return 1.0f - __fdividef(2.0f, e + 1.0f);
}

// Split-K GEMM with fused stride-4 gather, 128x128 block tile, 8x8 thread tile.
// grid = (4 M-tiles, 32 K-splits), block = 256.
// M-tiles 0..2 -> aud rows 0..383 (f1/W1); M-tile 3 -> vis rows 0..127 (f2/W2).
__global__ __launch_bounds__(256) void gemm_kernel(
    const float* __restrict__ f1, const float* __restrict__ f2,
    const float* __restrict__ W1, const float* __restrict__ W2)
{
    __shared__ __align__(16) float As[2][128][KS];   // [buf][row][kk] 32KB
    __shared__ __align__(16) float Ws[2][KS][128];   // [buf][kk][col] 32KB

    const int tid = threadIdx.x;
    const int wid = tid >> 5, lane = tid & 31;
    const int mt = blockIdx.x;
    const bool isVis = (mt == 3);
    const float* __restrict__ src = isVis ? f2 : f1;
    const float* __restrict__ Wm  = isVis ? W2 : W1;
    const int row0 = mt * 128;
    const int kc0 = blockIdx.y * KC;

    // compute-tile coordinates: 16 row-groups x 16 col-groups of 8
    const int tx  = lane & 15;                  // col group
    const int tyq = (wid << 1) | (lane >> 4);   // row group 0..15

    // A loader: warp w loads local rows [w*16, w*16+16), lane = kk
    const float* __restrict__ abase =
        src + (size_t)(isVis ? 0 : row0) * HW + (size_t)(wid * 16) * HW;
    // W loader: thread = (col, half)
    const int wcol = tid & 127, whalf = tid >> 7;
    const float* __restrict__ wbase = Wm + (size_t)wcol * KTOT + kc0;

    float aR[16];
    float4 wR[4];

    auto loadStage = [&](int s) {
        // all 32 d's of this stage live in one sampled H-row (640 = 4*160)
        int dbase = kc0 + s * KS;
        unsigned hh = (unsigned)dbase / 160u;
        unsigned ww0 = (unsigned)dbase - hh * 160u;
        size_t off = (size_t)hh * 2560u + (size_t)(ww0 + lane) * 4u;   // elems
#pragma unroll
        for (int r = 0; r < 16; ++r)
            aR[r] = __ldg(abase + (size_t)r * HW + off);
        const float* wp = wbase + s * KS;
#pragma unroll
        for (int t = 0; t < 4; ++t)
            wR[t] = *reinterpret_cast<const float4*>(wp + whalf * 4 + t * 8);
    };
    auto storeStage = [&](int buf) {
#pragma unroll
        for (int r = 0; r < 16; ++r)
            As[buf][wid * 16 + r][lane] = aR[r];
#pragma unroll
        for (int t = 0; t < 4; ++t) {
            int kk = whalf * 4 + t * 8;
            Ws[buf][kk + 0][wcol] = wR[t].x;
            Ws[buf][kk + 1][wcol] = wR[t].y;
            Ws[buf][kk + 2][wcol] = wR[t].z;
            Ws[buf][kk + 3][wcol] = wR[t].w;
        }
    };

    ull acc[8][4];
#pragma unroll
    for (int r = 0; r < 8; ++r)
#pragma unroll
        for (int c = 0; c < 4; ++c) acc[r][c] = 0ull;

    loadStage(0);
    storeStage(0);
    __syncthreads();

    for (int s = 0; s < NSTG; ++s) {
        int buf = s & 1;
        if (s + 1 < NSTG) loadStage(s + 1);
#pragma unroll
        for (int kk = 0; kk < KS; ++kk) {
            ulonglong2 w0 = *reinterpret_cast<const ulonglong2*>(&Ws[buf][kk][tx * 8]);
            ulonglong2 w1 = *reinterpret_cast<const ulonglong2*>(&Ws[buf][kk][tx * 8 + 4]);
#pragma unroll
            for (int r = 0; r < 8; ++r) {
                ull ad = dupf(As[buf][tyq * 8 + r][kk]);
                ffma2(acc[r][0], ad, w0.x);
                ffma2(acc[r][1], ad, w0.y);
                ffma2(acc[r][2], ad, w1.x);
                ffma2(acc[r][3], ad, w1.y);
            }
        }
        if (s + 1 < NSTG) storeStage(buf ^ 1);
        __syncthreads();
    }

    float* op0 = &g_part[blockIdx.y][row0 + tyq * 8][tx * 8];
#pragma unroll
    for (int r = 0; r < 8; ++r) {
        float4 v0 = make_float4(lo2(acc[r][0]), hi2(acc[r][0]), lo2(acc[r][1]), hi2(acc[r][1]));
        float4 v1 = make_float4(lo2(acc[r][2]), hi2(acc[r][2]), lo2(acc[r][3]), hi2(acc[r][3]));
        *reinterpret_cast<float4*>(op0 + (size_t)r * 128)     = v0;
        *reinterpret_cast<float4*>(op0 + (size_t)r * 128 + 4) = v1;
    }
}

// Per-(batch, modality) attention epilogue. grid = 256, block = 256.
#define SM_ENC   0
#define SM_VIS   384
#define SM_XAV   512
#define SM_WX    1280
#define SM_WH    1376
#define SM_WCS   1536
#define SM_ATT   9856
#define SM_TOTAL 26240   // floats -> 104960 bytes

__global__ __launch_bounds__(256) void attn_kernel(
    const float* __restrict__ b1, const float* __restrict__ b2,
    const float* __restrict__ Aa, const float* __restrict__ Av,
    const float* __restrict__ Wa, const float* __restrict__ Wv,
    const float* __restrict__ Wca, const float* __restrict__ Wcv,
    const float* __restrict__ Wha, const float* __restrict__ Whv,
    float* __restrict__ out)
{
    extern __shared__ __align__(16) float smem[];
    float* enc_a = smem + SM_ENC;
    float* visr  = smem + SM_VIS;
    float* XAv   = smem + SM_XAV;
    float* Wx_s  = smem + SM_WX;
    float* Wh_s  = smem + SM_WH;
    float* Wcs   = smem + SM_WCS;
    float* att   = smem + SM_ATT;
    float4* red  = reinterpret_cast<float4*>(att);   // alias, used before att

    const int tid = threadIdx.x;
    const int b = blockIdx.x >> 1;
    const int mod = blockIdx.x & 1;   // 0 = audio, 1 = visual

    // split-K reduction: 4 rows (aud c=0..2, vis) x 128 cols over 32 partials
    {
        int e = tid & 127;            // float4-entry: rl = e>>5 (row), q = e&31
        int half = tid >> 7;
        int rl = e >> 5, q = e & 31;
        int grow = (rl < 3) ? (b * 3 + rl) : (384 + b);
        float4 a4 = make_float4(0.f, 0.f, 0.f, 0.f);
#pragma unroll
        for (int s = 0; s < 16; ++s) {
            const float4 v = *reinterpret_cast<const float4*>(
                &g_part[half * 16 + s][grow][q * 4]);
            a4.x += v.x; a4.y += v.y; a4.z += v.z; a4.w += v.w;
        }
        red[tid] = a4;
    }
    if (tid < 96) {
        Wx_s[tid] = (mod ? Wv : Wa)[tid];
        Wh_s[tid] = (mod ? Whv : Wha)[tid];
    }
    const float* Wc = mod ? Wcv : Wca;
    for (int idx = tid; idx < 8192; idx += 256) {
        int h = idx >> 8, m = idx & 255;
        Wcs[h * 260 + m] = Wc[idx];
    }
    __syncthreads();

    if (tid < 128) {
        int rl = tid >> 5, q = tid & 31;
        float4 v0 = red[tid], v1 = red[128 + tid];
        float4 s4 = make_float4(v0.x + v1.x, v0.y + v1.y, v0.z + v1.z, v0.w + v1.w);
        if (rl < 3) {
            const float4 bb = *reinterpret_cast<const float4*>(&b1[q * 4]);
            float4 r4 = make_float4(s4.x + bb.x, s4.y + bb.y, s4.z + bb.z, s4.w + bb.w);
            *reinterpret_cast<float4*>(&enc_a[rl * 128 + q * 4]) = r4;
        } else {
            const float4 bb = *reinterpret_cast<const float4*>(&b2[q * 4]);
            float4 r4 = make_float4(s4.x + bb.x, s4.y + bb.y, s4.z + bb.z, s4.w + bb.w);
            *reinterpret_cast<float4*>(&visr[q * 4]) = r4;
        }
    }
    __syncthreads();

    const float* M = mod ? Av : Aa;
    {
        int m = tid;  // 0..255
        float av0 = (m < 128) ? enc_a[m]       : visr[m - 128];
        float av1 = (m < 128) ? enc_a[128 + m] : visr[m - 128];
        float av2 = (m < 128) ? enc_a[256 + m] : visr[m - 128];
        XAv[m]       = M[0] * av0 + M[1] * av1 + M[2] * av2;
        XAv[256 + m] = M[3] * av0 + M[4] * av1 + M[5] * av2;
        XAv[512 + m] = M[6] * av0 + M[7] * av1 + M[8] * av2;
    }
    __syncthreads();

    const int wid = tid >> 5, h = tid & 31;
    float* arow = att + wid * 2048;        // 8 rows x 256 per warp
    const float wx0 = Wx_s[h * 3], wx1 = Wx_s[h * 3 + 1], wx2 = Wx_s[h * 3 + 2];
    const float wh0 = Wh_s[h], wh1 = Wh_s[32 + h], wh2 = Wh_s[64 + h];
    const float scale = 0.0625f;   // 1/sqrt(256)

    for (int g = 0; g < 2; ++g) {
        const int k0 = wid * 16 + g * 8;

        float e0[8], e1[8], e2[8];
#pragma unroll
        for (int r = 0; r < 8; ++r) {
            int k = k0 + r;
            if (mod == 0) { e0[r] = enc_a[k]; e1[r] = enc_a[128 + k]; e2[r] = enc_a[256 + k]; }
            else          { e0[r] = visr[k];  e1[r] = e0[r];          e2[r] = e0[r]; }
        }

        // Phase 1: tanh rows into per-warp smem strip
#pragma unroll
        for (int mc = 0; mc < 8; ++mc) {
            int m = mc * 32 + h;
            float x0 = XAv[m], x1 = XAv[256 + m], x2 = XAv[512 + m];
#pragma unroll
            for (int r = 0; r < 8; ++r) {
                float s = e0[r] * x0 + e1[r] * x1 + e2[r] * x2;
                arow[r * 256 + m] = ftanh(s * scale);
            }
        }
        __syncwarp();

        // Phase 2: H[k][h] = relu(att_row . Wc[h] + e.Wx[h])
        ull acc[8];
#pragma unroll
        for (int r = 0; r < 8; ++r) acc[r] = 0ull;

        const ulonglong2* wrow = reinterpret_cast<const ulonglong2*>(Wcs + h * 260);
#pragma unroll 2
        for (int m4 = 0; m4 < 64; ++m4) {
            ulonglong2 wv = wrow[m4];
#pragma unroll
            for (int r = 0; r < 8; ++r) {
                ulonglong2 av = *reinterpret_cast<const ulonglong2*>(arow + r * 256 + m4 * 4);
                ffma2(acc[r], av.x, wv.x);
                ffma2(acc[r], av.y, wv.y);
            }
        }

#pragma unroll
        for (int r = 0; r < 8; ++r) {
            float pre = e0[r] * wx0 + e1[r] * wx1 + e2[r] * wx2;
            float Hh = fmaxf(lo2(acc[r]) + hi2(acc[r]) + pre, 0.0f);
            float r0 = Hh * wh0;
            float r1 = Hh * wh1;
            float r2 = Hh * wh2;
#pragma unroll
            for (int o = 16; o; o >>= 1) {
                r0 += __shfl_xor_sync(0xffffffffu, r0, o);
                r1 += __shfl_xor_sync(0xffffffffu, r1, o);
                r2 += __shfl_xor_sync(0xffffffffu, r2, o);
            }
            if (h == 0) {
                int k = k0 + r;
                float* ob = out + (size_t)b * 768 + mod * 128 + k;
                ob[0]   = r0 + e0[r];
                ob[256] = r1 + e1[r];
                ob[512] = r2 + e2[r];
            }
        }
        __syncwarp();
    }
}

extern "C" void kernel_launch(void* const* d_in, const int* in_sizes, int n_in,
                              void* d_out, int out_size)
{
    const float* f1  = (const float*)d_in[0];
    const float* f2  = (const float*)d_in[1];
    const float* W1  = (const float*)d_in[2];
    const float* b1  = (const float*)d_in[3];
    const float* W2  = (const float*)d_in[4];
    const float* b2  = (const float*)d_in[5];
    const float* Aa  = (const float*)d_in[6];
    const float* Av  = (const float*)d_in[7];
    const float* Wa  = (const float*)d_in[8];
    const float* Wv  = (const float*)d_in[9];
    const float* Wca = (const float*)d_in[10];
    const float* Wcv = (const float*)d_in[11];
    const float* Wha = (const float*)d_in[12];
    const float* Whv = (const float*)d_in[13];
    float* out = (float*)d_out;

    cudaFuncSetAttribute(attn_kernel, cudaFuncAttributeMaxDynamicSharedMemorySize,
                         SM_TOTAL * sizeof(float));

    dim3 g(4, SPLITK);
    gemm_kernel<<<g, 256>>>(f1, f2, W1, W2);
    attn_kernel<<<256, 256, SM_TOTAL * sizeof(float)>>>(
        b1, b2, Aa, Av, Wa, Wv, Wca, Wcv, Wha, Whv, out);
}

// round 7
// speedup vs baseline: 1.7627x; 1.3759x over previous
#include <cuda_runtime.h>
#include <cuda_bf16.h>
#include <cstdint>

#define HW 327680          // 512*640 per image
#define KTOT 20480
#define KC 640             // K per split-K block
#define KSTG 64            // K per pipeline stage
#define NST (KC / KSTG)    // 10
#define SPLITK 32

#define ST 36              // smem words per 64-k row (32 data + 4 pad)
#define WT (128 * ST)      // words per 128x64 bf16 tile = 4608
#define GEMM_SMEM (8 * WT * 4)   // Ah,Al,Bh,Bl x2 buffers = 147456 B

typedef unsigned long long ull;

__device__ float g_part[SPLITK][512][128];   // split-K partials

__device__ __forceinline__ uint32_t cvt2bf(float hi, float lo) {   // pack -> bf16x2
    uint32_t r;
    asm("cvt.rn.bf16x2.f32 %0, %1, %2;" : "=r"(r) : "f"(hi), "f"(lo));
    return r;
}
__device__ __forceinline__ void mma16816(float* d, const uint32_t* a, const uint32_t* b) {
    asm volatile(
        "mma.sync.aligned.m16n8k16.row.col.f32.bf16.bf16.f32 "
        "{%0,%1,%2,%3}, {%4,%5,%6,%7}, {%8,%9}, {%0,%1,%2,%3};"
        : "+f"(d[0]), "+f"(d[1]), "+f"(d[2]), "+f"(d[3])
        : "r"(a[0]), "r"(a[1]), "r"(a[2]), "r"(a[3]), "r"(b[0]), "r"(b[1]));
}
__device__ __forceinline__ void ffma2(ull& d, ull a, ull b) {
    asm("fma.rn.f32x2 %0, %1, %2, %3;" : "=l"(d) : "l"(a), "l"(b), "l"(d));
}
__device__ __forceinline__ float lo2(ull v) { return __uint_as_float((unsigned)v); }
__device__ __forceinline__ float hi2(ull v) { return __uint_as_float((unsigned)(v >> 32)); }
__device__ __forceinline__ float ftanh(float x) {
    float xc = fminf(fmaxf(x, -20.0f), 20.0f);
    float e = __expf(2.0f * xc);
    return 1.0f - __fdividef(2.0f, e + 1.0f);
}

// Split-K bf16 3-term HMMA GEMM with fused stride-4 gather.
// grid = (4 M-tiles, 32 K-splits), block = 256 (8 warps: 2 m x 4 n).
__global__ __launch_bounds__(256) void gemm_kernel(
    const float* __restrict__ f1, const float* __restrict__ f2,
    const float* __restrict__ W1, const float* __restrict__ W2)
{
    extern __shared__ __align__(16) uint32_t sm[];
    const int tid = threadIdx.x;
    const int wid = tid >> 5, lane = tid & 31;
    const int mt = blockIdx.x;
    const bool isVis = (mt == 3);
    const float* __restrict__ src = isVis ? f2 : f1;
    const float* __restrict__ Wm  = isVis ? W2 : W1;
    const int row0 = mt * 128;
    const int kc0 = blockIdx.y * KC;

    // A loader: kp = tid&31 (k-pair), rg = tid>>5 (16-row group)
    const int kp = tid & 31, rg = tid >> 5;
    const float* __restrict__ abase =
        src + (size_t)((isVis ? 0 : row0) + rg * 16) * HW;
    // W loader: wn = tid>>1 (n-row), whalf = tid&1 (32-k half)
    const int wn = tid >> 1, whalf = tid & 1;
    const float* __restrict__ wbase = Wm + (size_t)wn * KTOT + kc0;

    float a0[16], a1[16];
    float4 wv[8];

    auto loadStage = [&](int s) {
        int d0 = kc0 + s * KSTG + kp * 2;               // even, stays in one H-row
        unsigned hh = (unsigned)d0 / 160u;
        unsigned ww = (unsigned)d0 - hh * 160u;
        size_t off = (size_t)hh * 2560u + (size_t)ww * 4u;
#pragma unroll
        for (int j = 0; j < 16; ++j) {
            const float* p = abase + (size_t)j * HW + off;
            a0[j] = __ldg(p);
            a1[j] = __ldg(p + 4);
        }
        const float* wp = wbase + s * KSTG + whalf * 32;
#pragma unroll
        for (int q = 0; q < 8; ++q)
            wv[q] = *reinterpret_cast<const float4*>(wp + q * 4);
    };

    auto storeStage = [&](int buf) {
        uint32_t* Ah = sm + (size_t)buf * 4 * WT;
        uint32_t* Al = Ah + WT;
        uint32_t* Bh = Ah + 2 * WT;
        uint32_t* Bl = Ah + 3 * WT;
#pragma unroll
        for (int j = 0; j < 16; ++j) {
            int r = rg * 16 + j;
            float x0 = a0[j], x1 = a1[j];
            uint32_t hp = cvt2bf(x1, x0);
            float h0 = __uint_as_float(hp << 16);
            float h1 = __uint_as_float(hp & 0xffff0000u);
            uint32_t lp = cvt2bf(x1 - h1, x0 - h0);
            Ah[r * ST + kp] = hp;
            Al[r * ST + kp] = lp;
        }
#pragma unroll
        for (int q = 0; q < 8; ++q) {
            float4 v = wv[q];
            uint32_t hp0 = cvt2bf(v.y, v.x);
            uint32_t hp1 = cvt2bf(v.w, v.z);
            float h0 = __uint_as_float(hp0 << 16);
            float h1 = __uint_as_float(hp0 & 0xffff0000u);
            float h2 = __uint_as_float(hp1 << 16);
            float h3 = __uint_as_float(hp1 & 0xffff0000u);
            uint32_t lp0 = cvt2bf(v.y - h1, v.x - h0);
            uint32_t lp1 = cvt2bf(v.w - h3, v.z - h2);
            int w0 = wn * ST + whalf * 16 + 2 * q;
            *reinterpret_cast<uint2*>(Bh + w0) = make_uint2(hp0, hp1);
            *reinterpret_cast<uint2*>(Bl + w0) = make_uint2(lp0, lp1);
        }
    };

    const int wm = wid >> 2, wnw = wid & 3;   // warp tile: rows wm*64, cols wnw*32
    const int l4 = lane >> 2, lm = lane & 3;

    float acc[4][4][4];
#pragma unroll
    for (int i = 0; i < 4; ++i)
#pragma unroll
        for (int j = 0; j < 4; ++j)
#pragma unroll
            for (int c = 0; c < 4; ++c) acc[i][j][c] = 0.0f;

    loadStage(0);
    storeStage(0);
    __syncthreads();

    for (int s = 0; s < NST; ++s) {
        int buf = s & 1;
        if (s + 1 < NST) loadStage(s + 1);

        const uint32_t* Ah = sm + (size_t)buf * 4 * WT;
        const uint32_t* Al = Ah + WT;
        const uint32_t* Bh = Ah + 2 * WT;
        const uint32_t* Bl = Ah + 3 * WT;

#pragma unroll
        for (int kb = 0; kb < 4; ++kb) {            // k-step of 16 = 8 words
            const int ko = kb * 8 + lm;
            uint32_t ah[4][4], al[4][4], bh[4][2], bl[4][2];
#pragma unroll
            for (int i = 0; i < 4; ++i) {
                const uint32_t* p = Ah + (wm * 64 + i * 16 + l4) * ST + ko;
                ah[i][0] = p[0]; ah[i][1] = p[8 * ST]; ah[i][2] = p[4]; ah[i][3] = p[8 * ST + 4];
                const uint32_t* q = Al + (wm * 64 + i * 16 + l4) * ST + ko;
                al[i][0] = q[0]; al[i][1] = q[8 * ST]; al[i][2] = q[4]; al[i][3] = q[8 * ST + 4];
            }
#pragma unroll
            for (int j = 0; j < 4; ++j) {
                const uint32_t* p = Bh + (wnw * 32 + j * 8 + l4) * ST + ko;
                bh[j][0] = p[0]; bh[j][1] = p[4];
                const uint32_t* q = Bl + (wnw * 32 + j * 8 + l4) * ST + ko;
                bl[j][0] = q[0]; bl[j][1] = q[4];
            }
#pragma unroll
            for (int i = 0; i < 4; ++i)
#pragma unroll
                for (int j = 0; j < 4; ++j) {
                    mma16816(acc[i][j], ah[i], bh[j]);
                    mma16816(acc[i][j], ah[i], bl[j]);
                    mma16816(acc[i][j], al[i], bh[j]);
                }
        }

        __syncthreads();
        if (s + 1 < NST) {
            storeStage(buf ^ 1);
            __syncthreads();
        }
    }

    // epilogue: write 64x32 warp tile to g_part
#pragma unroll
    for (int i = 0; i < 4; ++i) {
        int rlo = row0 + wm * 64 + i * 16 + l4;
#pragma unroll
        for (int j = 0; j < 4; ++j) {
            int col = wnw * 32 + j * 8 + 2 * lm;
            *reinterpret_cast<float2*>(&g_part[blockIdx.y][rlo][col]) =
                make_float2(acc[i][j][0], acc[i][j][1]);
            *reinterpret_cast<float2*>(&g_part[blockIdx.y][rlo + 8][col]) =
                make_float2(acc[i][j][2], acc[i][j][3]);
        }
    }
}

// Per-(batch, modality) attention epilogue. grid = 256, block = 256.
#define SM_ENC   0
#define SM_VIS   384
#define SM_XAV   512
#define SM_WX    1280
#define SM_WH    1376
#define SM_WCS   1536
#define SM_ATT   9856
#define SM_TOTAL 18048   // floats -> 72192 bytes (3 blocks/SM)

__global__ __launch_bounds__(256) void attn_kernel(
    const float* __restrict__ b1, const float* __restrict__ b2,
    const float* __restrict__ Aa, const float* __restrict__ Av,
    const float* __restrict__ Wa, const float* __restrict__ Wv,
    const float* __restrict__ Wca, const float* __restrict__ Wcv,
    const float* __restrict__ Wha, const float* __restrict__ Whv,
    float* __restrict__ out)
{
    extern __shared__ __align__(16) float fsm[];
    float* enc_a = fsm + SM_ENC;
    float* visr  = fsm + SM_VIS;
    float* XAv   = fsm + SM_XAV;
    float* Wx_s  = fsm + SM_WX;
    float* Wh_s  = fsm + SM_WH;
    float* Wcs   = fsm + SM_WCS;
    float* att   = fsm + SM_ATT;
    float4* red  = reinterpret_cast<float4*>(att);   // alias, used before att

    const int tid = threadIdx.x;
    const int b = blockIdx.x >> 1;
    const int mod = blockIdx.x & 1;   // 0 = audio, 1 = visual

    // split-K reduction: 4 rows (aud c=0..2, vis) x 128 cols over 32 partials
    {
        int e = tid & 127;
        int half = tid >> 7;
        int rl = e >> 5, q = e & 31;
        int grow = (rl < 3) ? (b * 3 + rl) : (384 + b);
        float4 a4 = make_float4(0.f, 0.f, 0.f, 0.f);
#pragma unroll
        for (int s = 0; s < 16; ++s) {
            const float4 v = *reinterpret_cast<const float4*>(
                &g_part[half * 16 + s][grow][q * 4]);
            a4.x += v.x; a4.y += v.y; a4.z += v.z; a4.w += v.w;
        }
        red[tid] = a4;
    }
    if (tid < 96) {
        Wx_s[tid] = (mod ? Wv : Wa)[tid];
        Wh_s[tid] = (mod ? Whv : Wha)[tid];
    }
    const float* Wc = mod ? Wcv : Wca;
    for (int idx = tid; idx < 8192; idx += 256) {
        int h = idx >> 8, m = idx & 255;
        Wcs[h * 260 + m] = Wc[idx];
    }
    __syncthreads();

    if (tid < 128) {
        int rl = tid >> 5, q = tid & 31;
        float4 v0 = red[tid], v1 = red[128 + tid];
        float4 s4 = make_float4(v0.x + v1.x, v0.y + v1.y, v0.z + v1.z, v0.w + v1.w);
        if (rl < 3) {
            const float4 bb = *reinterpret_cast<const float4*>(&b1[q * 4]);
            *reinterpret_cast<float4*>(&enc_a[rl * 128 + q * 4]) =
                make_float4(s4.x + bb.x, s4.y + bb.y, s4.z + bb.z, s4.w + bb.w);
        } else {
            const float4 bb = *reinterpret_cast<const float4*>(&b2[q * 4]);
            *reinterpret_cast<float4*>(&visr[q * 4]) =
                make_float4(s4.x + bb.x, s4.y + bb.y, s4.z + bb.z, s4.w + bb.w);
        }
    }
    __syncthreads();

    const float* M = mod ? Av : Aa;
    {
        int m = tid;
        float av0 = (m < 128) ? enc_a[m]       : visr[m - 128];
        float av1 = (m < 128) ? enc_a[128 + m] : visr[m - 128];
        float av2 = (m < 128) ? enc_a[256 + m] : visr[m - 128];
        XAv[m]       = M[0] * av0 + M[1] * av1 + M[2] * av2;
        XAv[256 + m] = M[3] * av0 + M[4] * av1 + M[5] * av2;
        XAv[512 + m] = M[6] * av0 + M[7] * av1 + M[8] * av2;
    }
    __syncthreads();

    const int wid = tid >> 5, h = tid & 31;
    float* arow = att + wid * 1024;        // 4 rows x 256 per warp
    const float wx0 = Wx_s[h * 3], wx1 = Wx_s[h * 3 + 1], wx2 = Wx_s[h * 3 + 2];
    const float wh0 = Wh_s[h], wh1 = Wh_s[32 + h], wh2 = Wh_s[64 + h];
    const float scale = 0.0625f;

    for (int g = 0; g < 4; ++g) {
        const int k0 = wid * 16 + g * 4;

        float e0[4], e1[4], e2[4];
#pragma unroll
        for (int r = 0; r < 4; ++r) {
            int k = k0 + r;
            if (mod == 0) { e0[r] = enc_a[k]; e1[r] = enc_a[128 + k]; e2[r] = enc_a[256 + k]; }
            else          { e0[r] = visr[k];  e1[r] = e0[r];          e2[r] = e0[r]; }
        }

#pragma unroll
        for (int mc = 0; mc < 8; ++mc) {
            int m = mc * 32 + h;
            float x0 = XAv[m], x1 = XAv[256 + m], x2 = XAv[512 + m];
#pragma unroll
            for (int r = 0; r < 4; ++r) {
                float s = e0[r] * x0 + e1[r] * x1 + e2[r] * x2;
                arow[r * 256 + m] = ftanh(s * scale);
            }
        }
        __syncwarp();

        ull acc[4];
#pragma unroll
        for (int r = 0; r < 4; ++r) acc[r] = 0ull;

        const ulonglong2* wrow = reinterpret_cast<const ulonglong2*>(Wcs + h * 260);
#pragma unroll 4
        for (int m4 = 0; m4 < 64; ++m4) {
            ulonglong2 wv = wrow[m4];
#pragma unroll
            for (int r = 0; r < 4; ++r) {
                ulonglong2 av = *reinterpret_cast<const ulonglong2*>(arow + r * 256 + m4 * 4);
                ffma2(acc[r], av.x, wv.x);
                ffma2(acc[r], av.y, wv.y);
            }
        }

#pragma unroll
        for (int r = 0; r < 4; ++r) {
            float pre = e0[r] * wx0 + e1[r] * wx1 + e2[r] * wx2;
            float Hh = fmaxf(lo2(acc[r]) + hi2(acc[r]) + pre, 0.0f);
            float r0 = Hh * wh0;
            float r1 = Hh * wh1;
            float r2 = Hh * wh2;
#pragma unroll
            for (int o = 16; o; o >>= 1) {
                r0 += __shfl_xor_sync(0xffffffffu, r0, o);
                r1 += __shfl_xor_sync(0xffffffffu, r1, o);
                r2 += __shfl_xor_sync(0xffffffffu, r2, o);
            }
            if (h == 0) {
                int k = k0 + r;
                float* ob = out + (size_t)b * 768 + mod * 128 + k;
                ob[0]   = r0 + e0[r];
                ob[256] = r1 + e1[r];
                ob[512] = r2 + e2[r];
            }
        }
        __syncwarp();
    }
}

extern "C" void kernel_launch(void* const* d_in, const int* in_sizes, int n_in,
                              void* d_out, int out_size)
{
    const float* f1  = (const float*)d_in[0];
    const float* f2  = (const float*)d_in[1];
    const float* W1  = (const float*)d_in[2];
    const float* b1  = (const float*)d_in[3];
    const float* W2  = (const float*)d_in[4];
    const float* b2  = (const float*)d_in[5];
    const float* Aa  = (const float*)d_in[6];
    const float* Av  = (const float*)d_in[7];
    const float* Wa  = (const float*)d_in[8];
    const float* Wv  = (const float*)d_in[9];
    const float* Wca = (const float*)d_in[10];
    const float* Wcv = (const float*)d_in[11];
    const float* Wha = (const float*)d_in[12];
    const float* Whv = (const float*)d_in[13];
    float* out = (float*)d_out;

    cudaFuncSetAttribute(gemm_kernel, cudaFuncAttributeMaxDynamicSharedMemorySize,
                         GEMM_SMEM);
    cudaFuncSetAttribute(attn_kernel, cudaFuncAttributeMaxDynamicSharedMemorySize,
                         SM_TOTAL * sizeof(float));

    dim3 g(4, SPLITK);
    gemm_kernel<<<g, 256, GEMM_SMEM>>>(f1, f2, W1, W2);
    attn_kernel<<<256, 256, SM_TOTAL * sizeof(float)>>>(
        b1, b2, Aa, Av, Wa, Wv, Wca, Wcv, Wha, Whv, out);
}

// round 8
// speedup vs baseline: 1.7846x; 1.0124x over previous
#include <cuda_runtime.h>
#include <cuda_bf16.h>
#include <cstdint>

#define HW 327680          // 512*640 per image
#define KTOT 20480
#define KC 640             // K per split-K block
#define KSTG 64            // K per pipeline stage
#define NST (KC / KSTG)    // 10
#define SPLITK 32

#define ST 36              // smem words per 64-k row (32 data + 4 pad)
#define WT (128 * ST)      // words per 128x64 bf16 tile = 4608
#define GEMM_SMEM (8 * WT * 4)   // Ah,Al,Bh,Bl x2 buffers = 147456 B

typedef unsigned long long ull;

__device__ float g_part[SPLITK][512][128];   // split-K partials

__device__ __forceinline__ uint32_t cvt2bf(float hi, float lo) {   // pack -> bf16x2
    uint32_t r;
    asm("cvt.rn.bf16x2.f32 %0, %1, %2;" : "=r"(r) : "f"(hi), "f"(lo));
    return r;
}
__device__ __forceinline__ void mma16816(float* d, const uint32_t* a, const uint32_t* b) {
    asm volatile(
        "mma.sync.aligned.m16n8k16.row.col.f32.bf16.bf16.f32 "
        "{%0,%1,%2,%3}, {%4,%5,%6,%7}, {%8,%9}, {%0,%1,%2,%3};"
        : "+f"(d[0]), "+f"(d[1]), "+f"(d[2]), "+f"(d[3])
        : "r"(a[0]), "r"(a[1]), "r"(a[2]), "r"(a[3]), "r"(b[0]), "r"(b[1]));
}
__device__ __forceinline__ void ffma2(ull& d, ull a, ull b) {
    asm("fma.rn.f32x2 %0, %1, %2, %3;" : "=l"(d) : "l"(a), "l"(b), "l"(d));
}
__device__ __forceinline__ float lo2(ull v) { return __uint_as_float((unsigned)v); }
__device__ __forceinline__ float hi2(ull v) { return __uint_as_float((unsigned)(v >> 32)); }
__device__ __forceinline__ float ftanh(float x) {
    float xc = fminf(fmaxf(x, -20.0f), 20.0f);
    float e = __expf(2.0f * xc);
    return 1.0f - __fdividef(2.0f, e + 1.0f);
}

// Split-K bf16 3-term HMMA GEMM with fused stride-4 gather.
// grid = (4 M-tiles, 32 K-splits), block = 256 (8 warps: 2 m x 4 n).
__global__ __launch_bounds__(256) void gemm_kernel(
    const float* __restrict__ f1, const float* __restrict__ f2,
    const float* __restrict__ W1, const float* __restrict__ W2)
{
    extern __shared__ __align__(16) uint32_t sm[];
    const int tid = threadIdx.x;
    const int wid = tid >> 5, lane = tid & 31;
    const int mt = blockIdx.x;
    const bool isVis = (mt == 3);
    const float* __restrict__ src = isVis ? f2 : f1;
    const float* __restrict__ Wm  = isVis ? W2 : W1;
    const int row0 = mt * 128;
    const int kc0 = blockIdx.y * KC;

    // A loader: kp = tid&31 (k-pair), rg = tid>>5 (16-row group)
    const int kp = tid & 31, rg = tid >> 5;
    const float* __restrict__ abase =
        src + (size_t)((isVis ? 0 : row0) + rg * 16) * HW;
    // W loader: wn = tid>>1 (n-row), whalf = tid&1 (32-k half)
    const int wn = tid >> 1, whalf = tid & 1;
    const float* __restrict__ wbase = Wm + (size_t)wn * KTOT + kc0;

    float a0[16], a1[16];
    float4 wv[8];

    auto loadStage = [&](int s) {
        int d0 = kc0 + s * KSTG + kp * 2;               // even, stays in one H-row
        unsigned hh = (unsigned)d0 / 160u;
        unsigned ww = (unsigned)d0 - hh * 160u;
        size_t off = (size_t)hh * 2560u + (size_t)ww * 4u;
#pragma unroll
        for (int j = 0; j < 16; ++j) {
            const float* p = abase + (size_t)j * HW + off;
            a0[j] = __ldg(p);
            a1[j] = __ldg(p + 4);
        }
        const float* wp = wbase + s * KSTG + whalf * 32;
#pragma unroll
        for (int q = 0; q < 8; ++q)
            wv[q] = *reinterpret_cast<const float4*>(wp + q * 4);
    };

    auto storeStage = [&](int buf) {
        uint32_t* Ah = sm + (size_t)buf * 4 * WT;
        uint32_t* Al = Ah + WT;
        uint32_t* Bh = Ah + 2 * WT;
        uint32_t* Bl = Ah + 3 * WT;
#pragma unroll
        for (int j = 0; j < 16; ++j) {
            int r = rg * 16 + j;
            float x0 = a0[j], x1 = a1[j];
            uint32_t hp = cvt2bf(x1, x0);
            float h0 = __uint_as_float(hp << 16);
            float h1 = __uint_as_float(hp & 0xffff0000u);
            uint32_t lp = cvt2bf(x1 - h1, x0 - h0);
            Ah[r * ST + kp] = hp;
            Al[r * ST + kp] = lp;
        }
#pragma unroll
        for (int q = 0; q < 8; ++q) {
            float4 v = wv[q];
            uint32_t hp0 = cvt2bf(v.y, v.x);
            uint32_t hp1 = cvt2bf(v.w, v.z);
            float h0 = __uint_as_float(hp0 << 16);
            float h1 = __uint_as_float(hp0 & 0xffff0000u);
            float h2 = __uint_as_float(hp1 << 16);
            float h3 = __uint_as_float(hp1 & 0xffff0000u);
            uint32_t lp0 = cvt2bf(v.y - h1, v.x - h0);
            uint32_t lp1 = cvt2bf(v.w - h3, v.z - h2);
            int w0 = wn * ST + whalf * 16 + 2 * q;
            *reinterpret_cast<uint2*>(Bh + w0) = make_uint2(hp0, hp1);
            *reinterpret_cast<uint2*>(Bl + w0) = make_uint2(lp0, lp1);
        }
    };

    const int wm = wid >> 2, wnw = wid & 3;   // warp tile: rows wm*64, cols wnw*32
    const int l4 = lane >> 2, lm = lane & 3;

    float acc[4][4][4];
#pragma unroll
    for (int i = 0; i < 4; ++i)
#pragma unroll
        for (int j = 0; j < 4; ++j)
#pragma unroll
            for (int c = 0; c < 4; ++c) acc[i][j][c] = 0.0f;

    loadStage(0);
    storeStage(0);
    __syncthreads();

    for (int s = 0; s < NST; ++s) {
        int buf = s & 1;
        if (s + 1 < NST) loadStage(s + 1);

        const uint32_t* Ah = sm + (size_t)buf * 4 * WT;
        const uint32_t* Al = Ah + WT;
        const uint32_t* Bh = Ah + 2 * WT;
        const uint32_t* Bl = Ah + 3 * WT;

#pragma unroll
        for (int kb = 0; kb < 4; ++kb) {            // k-step of 16 = 8 words
            const int ko = kb * 8 + lm;
            uint32_t ah[4][4], al[4][4], bh[4][2], bl[4][2];
#pragma unroll
            for (int i = 0; i < 4; ++i) {
                const uint32_t* p = Ah + (wm * 64 + i * 16 + l4) * ST + ko;
                ah[i][0] = p[0]; ah[i][1] = p[8 * ST]; ah[i][2] = p[4]; ah[i][3] = p[8 * ST + 4];
                const uint32_t* q = Al + (wm * 64 + i * 16 + l4) * ST + ko;
                al[i][0] = q[0]; al[i][1] = q[8 * ST]; al[i][2] = q[4]; al[i][3] = q[8 * ST + 4];
            }
#pragma unroll
            for (int j = 0; j < 4; ++j) {
                const uint32_t* p = Bh + (wnw * 32 + j * 8 + l4) * ST + ko;
                bh[j][0] = p[0]; bh[j][1] = p[4];
                const uint32_t* q = Bl + (wnw * 32 + j * 8 + l4) * ST + ko;
                bl[j][0] = q[0]; bl[j][1] = q[4];
            }
#pragma unroll
            for (int i = 0; i < 4; ++i)
#pragma unroll
                for (int j = 0; j < 4; ++j) {
                    mma16816(acc[i][j], ah[i], bh[j]);
                    mma16816(acc[i][j], ah[i], bl[j]);
                    mma16816(acc[i][j], al[i], bh[j]);
                }
        }

        __syncthreads();
        if (s + 1 < NST) {
            storeStage(buf ^ 1);
            __syncthreads();
        }
    }

    // epilogue: write 64x32 warp tile to g_part
#pragma unroll
    for (int i = 0; i < 4; ++i) {
        int rlo = row0 + wm * 64 + i * 16 + l4;
#pragma unroll
        for (int j = 0; j < 4; ++j) {
            int col = wnw * 32 + j * 8 + 2 * lm;
            *reinterpret_cast<float2*>(&g_part[blockIdx.y][rlo][col]) =
                make_float2(acc[i][j][0], acc[i][j][1]);
            *reinterpret_cast<float2*>(&g_part[blockIdx.y][rlo + 8][col]) =
                make_float2(acc[i][j][2], acc[i][j][3]);
        }
    }
}

// Per-(batch, modality) attention epilogue. grid = 256, block = 256.
#define SM_ENC   0
#define SM_VIS   384
#define SM_XAV   512
#define SM_WX    1280
#define SM_WH    1376
#define SM_WCS   1536
#define SM_ATT   9856
#define SM_TOTAL 18048   // floats -> 72192 bytes (3 blocks/SM)

__global__ __launch_bounds__(256) void attn_kernel(
    const float* __restrict__ b1, const float* __restrict__ b2,
    const float* __restrict__ Aa, const float* __restrict__ Av,
    const float* __restrict__ Wa, const float* __restrict__ Wv,
    const float* __restrict__ Wca, const float* __restrict__ Wcv,
    const float* __restrict__ Wha, const float* __restrict__ Whv,
    float* __restrict__ out)
{
    extern __shared__ __align__(16) float fsm[];
    float* enc_a = fsm + SM_ENC;
    float* visr  = fsm + SM_VIS;
    float* XAv   = fsm + SM_XAV;
    float* Wx_s  = fsm + SM_WX;
    float* Wh_s  = fsm + SM_WH;
    float* Wcs   = fsm + SM_WCS;
    float* att   = fsm + SM_ATT;
    float4* red  = reinterpret_cast<float4*>(att);   // alias, used before att

    const int tid = threadIdx.x;
    const int b = blockIdx.x >> 1;
    const int mod = blockIdx.x & 1;   // 0 = audio, 1 = visual

    // split-K reduction: 4 rows (aud c=0..2, vis) x 128 cols over 32 partials
    {
        int e = tid & 127;
        int half = tid >> 7;
        int rl = e >> 5, q = e & 31;
        int grow = (rl < 3) ? (b * 3 + rl) : (384 + b);
        float4 a4 = make_float4(0.f, 0.f, 0.f, 0.f);
#pragma unroll
        for (int s = 0; s < 16; ++s) {
            const float4 v = *reinterpret_cast<const float4*>(
                &g_part[half * 16 + s][grow][q * 4]);
            a4.x += v.x; a4.y += v.y; a4.z += v.z; a4.w += v.w;
        }
        red[tid] = a4;
    }
    if (tid < 96) {
        Wx_s[tid] = (mod ? Wv : Wa)[tid];
        Wh_s[tid] = (mod ? Whv : Wha)[tid];
    }
    const float* Wc = mod ? Wcv : Wca;
    for (int idx = tid; idx < 8192; idx += 256) {
        int h = idx >> 8, m = idx & 255;
        Wcs[h * 260 + m] = Wc[idx];
    }
    __syncthreads();

    if (tid < 128) {
        int rl = tid >> 5, q = tid & 31;
        float4 v0 = red[tid], v1 = red[128 + tid];
        float4 s4 = make_float4(v0.x + v1.x, v0.y + v1.y, v0.z + v1.z, v0.w + v1.w);
        if (rl < 3) {
            const float4 bb = *reinterpret_cast<const float4*>(&b1[q * 4]);
            *reinterpret_cast<float4*>(&enc_a[rl * 128 + q * 4]) =
                make_float4(s4.x + bb.x, s4.y + bb.y, s4.z + bb.z, s4.w + bb.w);
        } else {
            const float4 bb = *reinterpret_cast<const float4*>(&b2[q * 4]);
            *reinterpret_cast<float4*>(&visr[q * 4]) =
                make_float4(s4.x + bb.x, s4.y + bb.y, s4.z + bb.z, s4.w + bb.w);
        }
    }
    __syncthreads();

    const float* M = mod ? Av : Aa;
    {
        int m = tid;
        float av0 = (m < 128) ? enc_a[m]       : visr[m - 128];
        float av1 = (m < 128) ? enc_a[128 + m] : visr[m - 128];
        float av2 = (m < 128) ? enc_a[256 + m] : visr[m - 128];
        XAv[m]       = M[0] * av0 + M[1] * av1 + M[2] * av2;
        XAv[256 + m] = M[3] * av0 + M[4] * av1 + M[5] * av2;
        XAv[512 + m] = M[6] * av0 + M[7] * av1 + M[8] * av2;
    }
    __syncthreads();

    const int wid = tid >> 5, h = tid & 31;
    float* arow = att + wid * 1024;        // 4 rows x 256 per warp
    const float wx0 = Wx_s[h * 3], wx1 = Wx_s[h * 3 + 1], wx2 = Wx_s[h * 3 + 2];
    const float wh0 = Wh_s[h], wh1 = Wh_s[32 + h], wh2 = Wh_s[64 + h];
    const float scale = 0.0625f;

    for (int g = 0; g < 4; ++g) {
        const int k0 = wid * 16 + g * 4;

        float e0[4], e1[4], e2[4];
#pragma unroll
        for (int r = 0; r < 4; ++r) {
            int k = k0 + r;
            if (mod == 0) { e0[r] = enc_a[k]; e1[r] = enc_a[128 + k]; e2[r] = enc_a[256 + k]; }
            else          { e0[r] = visr[k];  e1[r] = e0[r];          e2[r] = e0[r]; }
        }

#pragma unroll
        for (int mc = 0; mc < 8; ++mc) {
            int m = mc * 32 + h;
            float x0 = XAv[m], x1 = XAv[256 + m], x2 = XAv[512 + m];
#pragma unroll
            for (int r = 0; r < 4; ++r) {
                float s = e0[r] * x0 + e1[r] * x1 + e2[r] * x2;
                arow[r * 256 + m] = ftanh(s * scale);
            }
        }
        __syncwarp();

        ull acc[4];
#pragma unroll
        for (int r = 0; r < 4; ++r) acc[r] = 0ull;

        const ulonglong2* wrow = reinterpret_cast<const ulonglong2*>(Wcs + h * 260);
#pragma unroll 4
        for (int m4 = 0; m4 < 64; ++m4) {
            ulonglong2 wv = wrow[m4];
#pragma unroll
            for (int r = 0; r < 4; ++r) {
                ulonglong2 av = *reinterpret_cast<const ulonglong2*>(arow + r * 256 + m4 * 4);
                ffma2(acc[r], av.x, wv.x);
                ffma2(acc[r], av.y, wv.y);
            }
        }

#pragma unroll
        for (int r = 0; r < 4; ++r) {
            float pre = e0[r] * wx0 + e1[r] * wx1 + e2[r] * wx2;
            float Hh = fmaxf(lo2(acc[r]) + hi2(acc[r]) + pre, 0.0f);
            float r0 = Hh * wh0;
            float r1 = Hh * wh1;
            float r2 = Hh * wh2;
#pragma unroll
            for (int o = 16; o; o >>= 1) {
                r0 += __shfl_xor_sync(0xffffffffu, r0, o);
                r1 += __shfl_xor_sync(0xffffffffu, r1, o);
                r2 += __shfl_xor_sync(0xffffffffu, r2, o);
            }
            if (h == 0) {
                int k = k0 + r;
                float* ob = out + (size_t)b * 768 + mod * 128 + k;
                ob[0]   = r0 + e0[r];
                ob[256] = r1 + e1[r];
                ob[512] = r2 + e2[r];
            }
        }
        __syncwarp();
    }
}

extern "C" void kernel_launch(void* const* d_in, const int* in_sizes, int n_in,
                              void* d_out, int out_size)
{
    const float* f1  = (const float*)d_in[0];
    const float* f2  = (const float*)d_in[1];
    const float* W1  = (const float*)d_in[2];
    const float* b1  = (const float*)d_in[3];
    const float* W2  = (const float*)d_in[4];
    const float* b2  = (const float*)d_in[5];
    const float* Aa  = (const float*)d_in[6];
    const float* Av  = (const float*)d_in[7];
    const float* Wa  = (const float*)d_in[8];
    const float* Wv  = (const float*)d_in[9];
    const float* Wca = (const float*)d_in[10];
    const float* Wcv = (const float*)d_in[11];
    const float* Wha = (const float*)d_in[12];
    const float* Whv = (const float*)d_in[13];
    float* out = (float*)d_out;

    cudaFuncSetAttribute(gemm_kernel, cudaFuncAttributeMaxDynamicSharedMemorySize,
                         GEMM_SMEM);
    cudaFuncSetAttribute(attn_kernel, cudaFuncAttributeMaxDynamicSharedMemorySize,
                         SM_TOTAL * sizeof(float));

    dim3 g(4, SPLITK);
    gemm_kernel<<<g, 256, GEMM_SMEM>>>(f1, f2, W1, W2);
    attn_kernel<<<256, 256, SM_TOTAL * sizeof(float)>>>(
        b1, b2, Aa, Av, Wa, Wv, Wca, Wcv, Wha, Whv, out);
}